// round 7
// baseline (speedup 1.0000x reference)
#include <cuda_runtime.h>

#define BB 8
#define LL 512
#define DD 256
#define UU 32
#define SS 8    // query rows per block in the attention kernel

// Device scratch (no allocations allowed): QB = x@Wt + bh, K = x@Wx
__device__ float g_QB[BB * LL * UU];
__device__ float g_K [BB * LL * UU];

__device__ __forceinline__ float tanh_approx(float v) {
    float y;
    asm("tanh.approx.f32 %0, %1;" : "=f"(y) : "f"(v));
    return y;
}

// ---------------------------------------------------------------------------
// Kernel 1: per-row projections. Block handles 4 rows of x (256 floats each).
// Thread o<32 computes QB[row][o], o>=32 computes K[row][o-32].
// ---------------------------------------------------------------------------
__global__ __launch_bounds__(256) void qk_kernel(
    const float* __restrict__ x,
    const float* __restrict__ Wt,
    const float* __restrict__ Wx,
    const float* __restrict__ bh)
{
    __shared__ float xs[4 * DD];
    const int tid  = threadIdx.x;
    const int row0 = blockIdx.x * 4;

    ((float4*)xs)[tid] = ((const float4*)(x + (size_t)row0 * DD))[tid];
    __syncthreads();

    const int r = tid >> 6;          // 0..3 local row
    const int o = tid & 63;          // 0..63 output selector
    const int u = o & 31;
    const float* __restrict__ W = (o < 32) ? Wt : Wx;
    const float* xr = xs + r * DD;

    float acc = 0.f;
#pragma unroll 8
    for (int d = 0; d < DD; d++)
        acc = fmaf(xr[d], W[d * UU + u], acc);

    const int row = row0 + r;
    if (o < 32) g_QB[row * UU + u] = acc + bh[u];
    else        g_K [row * UU + u] = acc;
}

// ---------------------------------------------------------------------------
// Kernel 2: fused alpha + softmax + AV. One block per (b, 8-query tile).
// Scalar FFMA throughout (known-correct math from the 76.3us baseline);
// occupancy fix only: SS=16->8, 512 blocks, 3 blocks/SM guaranteed.
// ---------------------------------------------------------------------------
__global__ __launch_bounds__(256, 3) void attn_kernel(
    const float* __restrict__ x,
    const float* __restrict__ Wa,
    float* __restrict__ out)
{
    __shared__ float alpha_sm[SS][LL];   // 16 KB
    __shared__ float qb_sm[SS][UU];      // 1 KB
    __shared__ float wa_sm[UU];
    __shared__ float rinv_sm[SS];

    const int tid    = threadIdx.x;
    const int b      = blockIdx.x >> 6;          // L/SS = 64 tiles per batch
    const int s_base = (blockIdx.x & 63) * SS;

    if (tid < UU) wa_sm[tid] = Wa[tid];
    if (tid < (SS * UU) / 4)  // 64 float4 = 256 floats
        ((float4*)qb_sm)[tid] =
            ((const float4*)(g_QB + (size_t)(b * LL + s_base) * UU))[tid];
    __syncthreads();

    // ---- alpha[s][t] = sum_u tanh(qb[s][u] + K[t][u]) * Wa[u] -------------
    for (int half = 0; half < 2; half++) {
        const int t = tid + half * 256;
        const float4* kp  = (const float4*)(g_K + (size_t)(b * LL + t) * UU);
        const float4* wap = (const float4*)wa_sm;

        float acc[SS];
#pragma unroll
        for (int s = 0; s < SS; s++) acc[s] = 0.f;

#pragma unroll
        for (int u4 = 0; u4 < UU / 4; u4++) {
            const float4 kq = kp[u4];
            const float4 wq = wap[u4];
            const float kk[4] = {kq.x, kq.y, kq.z, kq.w};
            const float ww[4] = {wq.x, wq.y, wq.z, wq.w};
#pragma unroll
            for (int j = 0; j < 4; j++) {
                const int u = u4 * 4 + j;
#pragma unroll
                for (int s = 0; s < SS; s++)
                    acc[s] = fmaf(tanh_approx(qb_sm[s][u] + kk[j]), ww[j], acc[s]);
            }
        }
#pragma unroll
        for (int s = 0; s < SS; s++) alpha_sm[s][t] = acc[s];
    }
    __syncthreads();

    // ---- softmax over t, one warp per row (8 warps, 8 rows) ---------------
    const int warp = tid >> 5, lane = tid & 31;
    {
        const int s = warp;
        float m = -1e30f;
#pragma unroll
        for (int i = 0; i < LL / 32; i++)
            m = fmaxf(m, alpha_sm[s][lane + 32 * i]);
#pragma unroll
        for (int o = 16; o > 0; o >>= 1)
            m = fmaxf(m, __shfl_xor_sync(0xffffffffu, m, o));

        float sum = 0.f;
#pragma unroll
        for (int i = 0; i < LL / 32; i++) {
            const float e = __expf(alpha_sm[s][lane + 32 * i] - m);
            alpha_sm[s][lane + 32 * i] = e;
            sum += e;
        }
#pragma unroll
        for (int o = 16; o > 0; o >>= 1)
            sum += __shfl_xor_sync(0xffffffffu, sum, o);
        if (lane == 0) rinv_sm[s] = 1.0f / sum;
    }
    __syncthreads();

    // ---- AV: out[s][:] = (1/sum_s) * sum_t a[s][t] * x[b][t][:] -----------
    // Thread owns one float4 of D (d4) for 2 consecutive s rows.
    const int s0 = tid >> 6;     // 0..3 -> rows 2*s0, 2*s0+1
    const int d4 = tid & 63;     // 0..63
    const float4* xp = (const float4*)(x + (size_t)b * LL * DD) + d4;

    float4 acc[2];
    acc[0] = make_float4(0.f, 0.f, 0.f, 0.f);
    acc[1] = make_float4(0.f, 0.f, 0.f, 0.f);

    const float* a0 = &alpha_sm[2 * s0 + 0][0];
    const float* a1 = &alpha_sm[2 * s0 + 1][0];

#pragma unroll 8
    for (int t = 0; t < LL; t++) {
        const float4 xv = xp[(size_t)t * (DD / 4)];
        const float w0 = a0[t];
        const float w1 = a1[t];
        acc[0].x = fmaf(w0, xv.x, acc[0].x);
        acc[0].y = fmaf(w0, xv.y, acc[0].y);
        acc[0].z = fmaf(w0, xv.z, acc[0].z);
        acc[0].w = fmaf(w0, xv.w, acc[0].w);
        acc[1].x = fmaf(w1, xv.x, acc[1].x);
        acc[1].y = fmaf(w1, xv.y, acc[1].y);
        acc[1].z = fmaf(w1, xv.z, acc[1].z);
        acc[1].w = fmaf(w1, xv.w, acc[1].w);
    }

#pragma unroll
    for (int j = 0; j < 2; j++) {
        const int s = 2 * s0 + j;
        const float r = rinv_sm[s];
        const float4 v = make_float4(acc[j].x * r, acc[j].y * r,
                                     acc[j].z * r, acc[j].w * r);
        ((float4*)(out + (size_t)(b * LL + s_base + s) * DD))[d4] = v;
    }
}

extern "C" void kernel_launch(void* const* d_in, const int* in_sizes, int n_in,
                              void* d_out, int out_size)
{
    const float* x  = (const float*)d_in[0];
    const float* Wt = (const float*)d_in[1];
    const float* Wx = (const float*)d_in[2];
    const float* bh = (const float*)d_in[3];
    const float* Wa = (const float*)d_in[4];
    // d_in[5] = ba: uniform shift per softmax row -> cancels; intentionally unused.
    float* out = (float*)d_out;

    qk_kernel<<<(BB * LL) / 4, 256>>>(x, Wt, Wx, bh);
    attn_kernel<<<BB * (LL / SS), 256>>>(x, Wa, out);
}

// round 8
// speedup vs baseline: 1.0325x; 1.0325x over previous
#include <cuda_runtime.h>

#define BB 8
#define LL 512
#define DD 256
#define UU 32
#define SS 16   // query rows per block in the attention kernel

// Device scratch (no allocations allowed): QB = x@Wt + bh, K = x@Wx
__device__ float g_QB[BB * LL * UU];
__device__ float g_K [BB * LL * UU];

__device__ __forceinline__ float tanh_approx(float v) {
    float y;
    asm("tanh.approx.f32 %0, %1;" : "=f"(y) : "f"(v));
    return y;
}

// ---------------------------------------------------------------------------
// Kernel 1: per-row projections. Block handles 4 rows of x (256 floats each).
// Thread o<32 computes QB[row][o], o>=32 computes K[row][o-32].
// ---------------------------------------------------------------------------
__global__ __launch_bounds__(256) void qk_kernel(
    const float* __restrict__ x,
    const float* __restrict__ Wt,
    const float* __restrict__ Wx,
    const float* __restrict__ bh)
{
    __shared__ float xs[4 * DD];
    const int tid  = threadIdx.x;
    const int row0 = blockIdx.x * 4;

    ((float4*)xs)[tid] = ((const float4*)(x + (size_t)row0 * DD))[tid];
    __syncthreads();

    const int r = tid >> 6;          // 0..3 local row
    const int o = tid & 63;          // 0..63 output selector
    const int u = o & 31;
    const float* __restrict__ W = (o < 32) ? Wt : Wx;
    const float* xr = xs + r * DD;

    float acc = 0.f;
#pragma unroll 8
    for (int d = 0; d < DD; d++)
        acc = fmaf(xr[d], W[d * UU + u], acc);

    const int row = row0 + r;
    if (o < 32) g_QB[row * UU + u] = acc + bh[u];
    else        g_K [row * UU + u] = acc;
}

// ---------------------------------------------------------------------------
// Kernel 2: fused alpha + softmax + AV. One block per (b, 16-query tile).
// alpha + softmax identical to the verified 76.3us baseline.
// AV restructured: 64 d4 x 2 s-groups(8 rows) x 2 t-halves
//   -> LDG count halved, 32 FFMA per LDG.128, in-block t-half reduction.
// ---------------------------------------------------------------------------
__global__ __launch_bounds__(256, 2) void attn_kernel(
    const float* __restrict__ x,
    const float* __restrict__ Wa,
    float* __restrict__ out)
{
    __shared__ __align__(16) float alpha_sm[SS][LL];  // 32 KB (reused as AV scratch)
    __shared__ float qb_sm[SS][UU];                   // 2 KB
    __shared__ float wa_sm[UU];
    __shared__ float rinv_sm[SS];

    const int tid    = threadIdx.x;
    const int b      = blockIdx.x >> 5;          // L/SS = 32 tiles per batch
    const int s_base = (blockIdx.x & 31) * SS;

    if (tid < UU) wa_sm[tid] = Wa[tid];
    if (tid < (SS * UU) / 4)  // 128 float4 = 512 floats
        ((float4*)qb_sm)[tid] =
            ((const float4*)(g_QB + (size_t)(b * LL + s_base) * UU))[tid];
    __syncthreads();

    // ---- alpha[s][t] = sum_u tanh(qb[s][u] + K[t][u]) * Wa[u] -------------
    for (int half = 0; half < 2; half++) {
        const int t = tid + half * 256;
        const float4* kp  = (const float4*)(g_K + (size_t)(b * LL + t) * UU);
        const float4* wap = (const float4*)wa_sm;

        float acc[SS];
#pragma unroll
        for (int s = 0; s < SS; s++) acc[s] = 0.f;

#pragma unroll
        for (int u4 = 0; u4 < UU / 4; u4++) {
            const float4 kq = kp[u4];
            const float4 wq = wap[u4];
            const float kk[4] = {kq.x, kq.y, kq.z, kq.w};
            const float ww[4] = {wq.x, wq.y, wq.z, wq.w};
#pragma unroll
            for (int j = 0; j < 4; j++) {
                const int u = u4 * 4 + j;
#pragma unroll
                for (int s = 0; s < SS; s++)
                    acc[s] = fmaf(tanh_approx(qb_sm[s][u] + kk[j]), ww[j], acc[s]);
            }
        }
#pragma unroll
        for (int s = 0; s < SS; s++) alpha_sm[s][t] = acc[s];
    }
    __syncthreads();

    // ---- softmax over t, one warp per row (8 warps x 2 rows) --------------
    const int warp = tid >> 5, lane = tid & 31;
#pragma unroll
    for (int rr = 0; rr < 2; rr++) {
        const int s = warp + rr * 8;
        float m = -1e30f;
#pragma unroll
        for (int i = 0; i < LL / 32; i++)
            m = fmaxf(m, alpha_sm[s][lane + 32 * i]);
#pragma unroll
        for (int o = 16; o > 0; o >>= 1)
            m = fmaxf(m, __shfl_xor_sync(0xffffffffu, m, o));

        float sum = 0.f;
#pragma unroll
        for (int i = 0; i < LL / 32; i++) {
            const float e = __expf(alpha_sm[s][lane + 32 * i] - m);
            alpha_sm[s][lane + 32 * i] = e;
            sum += e;
        }
#pragma unroll
        for (int o = 16; o > 0; o >>= 1)
            sum += __shfl_xor_sync(0xffffffffu, sum, o);
        if (lane == 0) rinv_sm[s] = 1.0f / sum;
    }
    __syncthreads();

    // ---- AV: out[s][:] = (1/sum_s) * sum_t a[s][t] * x[b][t][:] -----------
    // Thread = (d4, sg, th): d4 owns one float4 of D, sg owns 8 rows,
    // th owns one 256-wide t-half. 32 FFMA per LDG.128.
    const int d4 = tid & 63;         // 0..63
    const int sg = (tid >> 6) & 1;   // 0..1 -> rows sg*8 .. sg*8+7
    const int th = tid >> 7;         // 0..1 -> t in [th*256, th*256+256)
    const float4* xp = (const float4*)(x + (size_t)b * LL * DD) + d4;

    float4 acc[8];
#pragma unroll
    for (int j = 0; j < 8; j++) acc[j] = make_float4(0.f, 0.f, 0.f, 0.f);

    const int t0 = th * 256;
#pragma unroll 8
    for (int ti = 0; ti < 256; ti++) {
        const int t = t0 + ti;
        const float4 xv = xp[(size_t)t * (DD / 4)];
#pragma unroll
        for (int j = 0; j < 8; j++) {
            const float w = alpha_sm[sg * 8 + j][t];
            acc[j].x = fmaf(w, xv.x, acc[j].x);
            acc[j].y = fmaf(w, xv.y, acc[j].y);
            acc[j].z = fmaf(w, xv.z, acc[j].z);
            acc[j].w = fmaf(w, xv.w, acc[j].w);
        }
    }

    // All alpha reads are done; reuse alpha_sm as reduction scratch.
    __syncthreads();
    float4 (*scratch)[128] = (float4(*)[128])&alpha_sm[0][0];  // [8][128] = 16KB
    const int pair = tid & 127;      // d4 + 64*sg

    if (th == 1) {
#pragma unroll
        for (int j = 0; j < 8; j++) scratch[j][pair] = acc[j];
    }
    __syncthreads();
    if (th == 0) {
#pragma unroll
        for (int j = 0; j < 8; j++) {
            const float4 p = scratch[j][pair];
            const int s = sg * 8 + j;
            const float r = rinv_sm[s];
            float4 v;
            v.x = (acc[j].x + p.x) * r;
            v.y = (acc[j].y + p.y) * r;
            v.z = (acc[j].z + p.z) * r;
            v.w = (acc[j].w + p.w) * r;
            ((float4*)(out + (size_t)(b * LL + s_base + s) * DD))[d4] = v;
        }
    }
}

extern "C" void kernel_launch(void* const* d_in, const int* in_sizes, int n_in,
                              void* d_out, int out_size)
{
    const float* x  = (const float*)d_in[0];
    const float* Wt = (const float*)d_in[1];
    const float* Wx = (const float*)d_in[2];
    const float* bh = (const float*)d_in[3];
    const float* Wa = (const float*)d_in[4];
    // d_in[5] = ba: uniform shift per softmax row -> cancels; intentionally unused.
    float* out = (float*)d_out;

    qk_kernel<<<(BB * LL) / 4, 256>>>(x, Wt, Wx, bh);
    attn_kernel<<<BB * (LL / SS), 256>>>(x, Wa, out);
}

// round 14
// speedup vs baseline: 1.6499x; 1.5980x over previous
#include <cuda_runtime.h>

#define BB 8
#define LL 512
#define DD 256
#define UU 32
#define SS 16   // query rows per block in the attention kernel

// Device scratch (no allocations allowed): QB = x@Wt + bh, K = x@Wx
__device__ float g_QB[BB * LL * UU];
__device__ float g_K [BB * LL * UU];

__device__ __forceinline__ float tanh_approx(float v) {
    float y;
    asm("tanh.approx.f32 %0, %1;" : "=f"(y) : "f"(v));
    return y;
}

// ---------------------------------------------------------------------------
// Kernel 1: per-row projections. Block handles 4 rows of x (256 floats each).
// Thread o<32 computes QB[row][o], o>=32 computes K[row][o-32].
// ---------------------------------------------------------------------------
__global__ __launch_bounds__(256) void qk_kernel(
    const float* __restrict__ x,
    const float* __restrict__ Wt,
    const float* __restrict__ Wx,
    const float* __restrict__ bh)
{
    __shared__ float xs[4 * DD];
    const int tid  = threadIdx.x;
    const int row0 = blockIdx.x * 4;

    ((float4*)xs)[tid] = ((const float4*)(x + (size_t)row0 * DD))[tid];
    __syncthreads();

    const int r = tid >> 6;          // 0..3 local row
    const int o = tid & 63;          // 0..63 output selector
    const int u = o & 31;
    const float* __restrict__ W = (o < 32) ? Wt : Wx;
    const float* xr = xs + r * DD;

    float acc = 0.f;
#pragma unroll 8
    for (int d = 0; d < DD; d++)
        acc = fmaf(xr[d], W[d * UU + u], acc);

    const int row = row0 + r;
    if (o < 32) g_QB[row * UU + u] = acc + bh[u];
    else        g_K [row * UU + u] = acc;
}

// ---------------------------------------------------------------------------
// Kernel 2: fused alpha + softmax + AV. One block per (b, 16-query tile).
// Math + memory pattern IDENTICAL to the verified 76.3us baseline (R1).
// Single change: __launch_bounds__(256, 3) -> 3 resident blocks/SM.
// ---------------------------------------------------------------------------
__global__ __launch_bounds__(256, 3) void attn_kernel(
    const float* __restrict__ x,
    const float* __restrict__ Wa,
    float* __restrict__ out)
{
    __shared__ float alpha_sm[SS][LL];   // 32 KB
    __shared__ float qb_sm[SS][UU];      // 2 KB
    __shared__ float wa_sm[UU];
    __shared__ float rinv_sm[SS];

    const int tid    = threadIdx.x;
    const int b      = blockIdx.x >> 5;          // L/SS = 32 tiles per batch
    const int s_base = (blockIdx.x & 31) * SS;

    if (tid < UU) wa_sm[tid] = Wa[tid];
    if (tid < (SS * UU) / 4)  // 128 float4 = 512 floats
        ((float4*)qb_sm)[tid] =
            ((const float4*)(g_QB + (size_t)(b * LL + s_base) * UU))[tid];
    __syncthreads();

    // ---- alpha[s][t] = sum_u tanh(qb[s][u] + K[t][u]) * Wa[u] -------------
    for (int half = 0; half < 2; half++) {
        const int t = tid + half * 256;
        const float4* kp  = (const float4*)(g_K + (size_t)(b * LL + t) * UU);
        const float4* wap = (const float4*)wa_sm;

        float acc[SS];
#pragma unroll
        for (int s = 0; s < SS; s++) acc[s] = 0.f;

#pragma unroll 2
        for (int u4 = 0; u4 < UU / 4; u4++) {
            const float4 kq = kp[u4];
            const float4 wq = wap[u4];
            const float kk[4] = {kq.x, kq.y, kq.z, kq.w};
            const float ww[4] = {wq.x, wq.y, wq.z, wq.w};
#pragma unroll
            for (int j = 0; j < 4; j++) {
                const int u = u4 * 4 + j;
#pragma unroll
                for (int s = 0; s < SS; s++)
                    acc[s] = fmaf(tanh_approx(qb_sm[s][u] + kk[j]), ww[j], acc[s]);
            }
        }
#pragma unroll
        for (int s = 0; s < SS; s++) alpha_sm[s][t] = acc[s];
    }
    __syncthreads();

    // ---- softmax over t, one warp per row (8 warps x 2 rows) --------------
    const int warp = tid >> 5, lane = tid & 31;
#pragma unroll
    for (int rr = 0; rr < 2; rr++) {
        const int s = warp + rr * 8;
        float m = -1e30f;
#pragma unroll
        for (int i = 0; i < LL / 32; i++)
            m = fmaxf(m, alpha_sm[s][lane + 32 * i]);
#pragma unroll
        for (int o = 16; o > 0; o >>= 1)
            m = fmaxf(m, __shfl_xor_sync(0xffffffffu, m, o));

        float sum = 0.f;
#pragma unroll
        for (int i = 0; i < LL / 32; i++) {
            const float e = __expf(alpha_sm[s][lane + 32 * i] - m);
            alpha_sm[s][lane + 32 * i] = e;
            sum += e;
        }
#pragma unroll
        for (int o = 16; o > 0; o >>= 1)
            sum += __shfl_xor_sync(0xffffffffu, sum, o);
        if (lane == 0) rinv_sm[s] = 1.0f / sum;
    }
    __syncthreads();

    // ---- AV: out[s][:] = (1/sum_s) * sum_t a[s][t] * x[b][t][:] -----------
    // Thread owns one float4 of D (d4) for 4 consecutive s rows.
    // (4 threads share each (d4,t) load -> trailing warps hit L1; keep it.)
    const int s0 = tid >> 6;     // 0..3
    const int d4 = tid & 63;     // 0..63
    const float4* xp = (const float4*)(x + (size_t)b * LL * DD) + d4;

    float4 acc[4];
#pragma unroll
    for (int j = 0; j < 4; j++) acc[j] = make_float4(0.f, 0.f, 0.f, 0.f);

#pragma unroll 4
    for (int t = 0; t < LL; t++) {
        const float4 xv = xp[(size_t)t * (DD / 4)];
#pragma unroll
        for (int j = 0; j < 4; j++) {
            const float a = alpha_sm[s0 * 4 + j][t];
            acc[j].x = fmaf(a, xv.x, acc[j].x);
            acc[j].y = fmaf(a, xv.y, acc[j].y);
            acc[j].z = fmaf(a, xv.z, acc[j].z);
            acc[j].w = fmaf(a, xv.w, acc[j].w);
        }
    }

#pragma unroll
    for (int j = 0; j < 4; j++) {
        const int s = s0 * 4 + j;
        const float r = rinv_sm[s];
        const float4 v = make_float4(acc[j].x * r, acc[j].y * r,
                                     acc[j].z * r, acc[j].w * r);
        ((float4*)(out + (size_t)(b * LL + s_base + s) * DD))[d4] = v;
    }
}

extern "C" void kernel_launch(void* const* d_in, const int* in_sizes, int n_in,
                              void* d_out, int out_size)
{
    const float* x  = (const float*)d_in[0];
    const float* Wt = (const float*)d_in[1];
    const float* Wx = (const float*)d_in[2];
    const float* bh = (const float*)d_in[3];
    const float* Wa = (const float*)d_in[4];
    // d_in[5] = ba: uniform shift per softmax row -> cancels; intentionally unused.
    float* out = (float*)d_out;

    qk_kernel<<<(BB * LL) / 4, 256>>>(x, Wt, Wx, bh);
    attn_kernel<<<BB * (LL / SS), 256>>>(x, Wa, out);
}